// round 12
// baseline (speedup 1.0000x reference)
#include <cuda_runtime.h>
#include <cuda_fp16.h>
#include <cstdint>

#define NN 100000
#define EE 1600000
#define DD 128

#define SCAN_THREADS 256
#define SCAN_PER_THREAD 8
#define SCAN_CHUNK (SCAN_THREADS * SCAN_PER_THREAD)   // 2048
#define SCAN_NB ((NN + SCAN_CHUNK - 1) / SCAN_CHUNK)  // 49

#define MEGA_BLOCKS 148
#define MEGA_THREADS 256

// xs[128][132] + ws[128][132] floats
#define GEMM_SMEM_BYTES ((128 * 132 + 128 * 132) * 4)

// Scratch (no device allocation allowed -> __device__ globals)
__device__ __half g_xwh[(size_t)NN * DD];   // x @ W fp16 (25.6 MB, L2-resident)
__device__ float  g_deg[NN];
__device__ float  g_dinv[NN];
__device__ int    g_cnt[NN];
__device__ int    g_incl[NN];
__device__ int    g_cursor[NN];
__device__ int    g_bsum[SCAN_NB];
__device__ int    g_boff[SCAN_NB];
__device__ int2   g_epack[EE];              // CSR-by-target: (src, coef bits)

// software grid barrier state (monotonic generation; work per launch identical)
__device__ unsigned g_mega_count = 0;
__device__ unsigned g_mega_gen   = 0;

__device__ __forceinline__ void grid_barrier() {
    __syncthreads();
    if (threadIdx.x == 0) {
        unsigned gen = ((volatile unsigned*)&g_mega_gen)[0];
        __threadfence();
        unsigned arrived = atomicAdd(&g_mega_count, 1u);
        if (arrived == MEGA_BLOCKS - 1) {
            g_mega_count = 0;
            __threadfence();
            atomicAdd(&g_mega_gen, 1u);
        } else {
            while (((volatile unsigned*)&g_mega_gen)[0] == gen) __nanosleep(64);
        }
        __threadfence();
    }
    __syncthreads();
}

// ---------------------------------------------------------------------------
// Persistent CSR-build kernel: init + accum + 3-phase scan + fill, with
// software grid barriers between phases. All 148 blocks are co-resident by
// construction (256 thr, <=64 regs, ~1KB smem per block), so barriers are
// deadlock-free; progress independent of the concurrently-running GEMM.
__global__ void __launch_bounds__(MEGA_THREADS, 4)
mega_csr_kernel(const int* __restrict__ ei, const float* __restrict__ ew) {
    __shared__ int sh[SCAN_THREADS];
    const int tid    = threadIdx.x;
    const int gid    = blockIdx.x * MEGA_THREADS + tid;
    const int stride = MEGA_BLOCKS * MEGA_THREADS;

    // phase 1: init (deg=1 self-loop, cnt=0)
    for (int i = gid; i < NN; i += stride) { g_deg[i] = 1.0f; g_cnt[i] = 0; }
    grid_barrier();

    // phase 2: degree + histogram at targets
    for (int e = gid; e < EE; e += stride) {
        int c = ei[EE + e];
        atomicAdd(&g_deg[c], ew[e]);
        atomicAdd(&g_cnt[c], 1);
    }
    grid_barrier();

    // phase 3a: per-chunk inclusive scan (blocks 0..SCAN_NB-1)
    if (blockIdx.x < SCAN_NB) {
        int base = blockIdx.x * SCAN_CHUNK + tid * SCAN_PER_THREAD;
        int v[SCAN_PER_THREAD];
        int sum = 0;
#pragma unroll
        for (int j = 0; j < SCAN_PER_THREAD; j++) {
            int idx = base + j;
            int c = (idx < NN) ? g_cnt[idx] : 0;
            sum += c;
            v[j] = sum;
        }
        sh[tid] = sum;
        __syncthreads();
        for (int off = 1; off < SCAN_THREADS; off <<= 1) {
            int t = (tid >= off) ? sh[tid - off] : 0;
            __syncthreads();
            sh[tid] += t;
            __syncthreads();
        }
        int prefix = (tid > 0) ? sh[tid - 1] : 0;
#pragma unroll
        for (int j = 0; j < SCAN_PER_THREAD; j++) {
            int idx = base + j;
            if (idx < NN) g_incl[idx] = v[j] + prefix;
        }
        if (tid == SCAN_THREADS - 1) g_bsum[blockIdx.x] = sh[SCAN_THREADS - 1];
    }
    grid_barrier();

    // phase 3b: scan the 49 block sums — ENTIRELY in warp 0 of block 0
    // (both halves loaded from global into registers; no cross-warp smem
    // handoff — the R11 bug was warp0 reading warp1's smem after __syncwarp).
    if (blockIdx.x == 0 && tid < 32) {
        int v0 = (tid < SCAN_NB) ? g_bsum[tid] : 0;
        int v1 = (tid + 32 < SCAN_NB) ? g_bsum[tid + 32] : 0;
        int a0 = v0, a1 = v1;
#pragma unroll
        for (int off = 1; off < 32; off <<= 1) {
            int t = __shfl_up_sync(0xffffffffu, a0, off);
            if (tid >= off) a0 += t;
        }
        int tot0 = __shfl_sync(0xffffffffu, a0, 31);
#pragma unroll
        for (int off = 1; off < 32; off <<= 1) {
            int t = __shfl_up_sync(0xffffffffu, a1, off);
            if (tid >= off) a1 += t;
        }
        a1 += tot0;
        if (tid < SCAN_NB)      g_boff[tid]      = a0 - v0;
        if (tid + 32 < SCAN_NB) g_boff[tid + 32] = a1 - v1;
    }
    grid_barrier();

    // phase 3c: finalize offsets + dinv
    for (int i = gid; i < NN; i += stride) {
        int incl = g_incl[i] + g_boff[i / SCAN_CHUNK];
        g_incl[i]   = incl;
        g_cursor[i] = incl - g_cnt[i];
        float d = g_deg[i];
        g_dinv[i] = (d > 0.0f) ? rsqrtf(d) : 0.0f;
    }
    grid_barrier();

    // phase 4: fill CSR (src, coef) bucketed by target
    for (int e = gid; e < EE; e += stride) {
        int row = ei[e];
        int col = ei[EE + e];
        float coef = g_dinv[row] * ew[e] * g_dinv[col];
        int pos = atomicAdd(&g_cursor[col], 1);
        g_epack[pos] = make_int2(row, __float_as_int(coef));
    }
}

// ---------------------------------------------------------------------------
// tf32 tensor-core GEMM: g_xwh (fp16) = x @ W.
__device__ __forceinline__ uint32_t f2tf32(float v) {
    uint32_t r;
    asm("cvt.rna.tf32.f32 %0, %1;" : "=r"(r) : "f"(v));
    return r;
}

__global__ void __launch_bounds__(256) gemm_kernel(const float* __restrict__ x,
                                                   const float* __restrict__ w) {
    extern __shared__ float smem[];
    float* xs = smem;               // [128 r][132 k] x tile (tf32 bits)
    float* ws = smem + 128 * 132;   // [128 k][132 n] W      (tf32 bits)

    const int tid  = threadIdx.x;
    const int base = blockIdx.x * 128;

    const float4* xg  = (const float4*)x;
    const float4* wg  = (const float4*)w;

#pragma unroll
    for (int i = 0; i < 16; i++) {
        int idx = tid + i * 256;
        int k   = idx >> 5;
        int n4  = idx & 31;
        float4 v = wg[idx];
        float4 t;
        t.x = __uint_as_float(f2tf32(v.x));
        t.y = __uint_as_float(f2tf32(v.y));
        t.z = __uint_as_float(f2tf32(v.z));
        t.w = __uint_as_float(f2tf32(v.w));
        ((float4*)ws)[k * 33 + n4] = t;
    }
#pragma unroll
    for (int i = 0; i < 16; i++) {
        int idx = tid + i * 256;
        int r   = idx >> 5;
        int k4  = idx & 31;
        float4 v = make_float4(0.f, 0.f, 0.f, 0.f);
        if (base + r < NN) v = xg[(size_t)(base + r) * 32 + k4];
        float4 t;
        t.x = __uint_as_float(f2tf32(v.x));
        t.y = __uint_as_float(f2tf32(v.y));
        t.z = __uint_as_float(f2tf32(v.z));
        t.w = __uint_as_float(f2tf32(v.w));
        ((float4*)xs)[r * 33 + k4] = t;
    }
    __syncthreads();

    const int warp = tid >> 5;
    const int lane = tid & 31;
    const int wrow = warp * 16;
    const int grp  = lane >> 2;
    const int thr  = lane & 3;

    float c[16][4];
#pragma unroll
    for (int nt = 0; nt < 16; nt++)
#pragma unroll
        for (int j = 0; j < 4; j++) c[nt][j] = 0.0f;

#pragma unroll
    for (int kt = 0; kt < 16; kt++) {
        int k0 = kt * 8;
        uint32_t a0 = __float_as_uint(xs[(wrow + grp)     * 132 + k0 + thr]);
        uint32_t a1 = __float_as_uint(xs[(wrow + grp + 8) * 132 + k0 + thr]);
        uint32_t a2 = __float_as_uint(xs[(wrow + grp)     * 132 + k0 + thr + 4]);
        uint32_t a3 = __float_as_uint(xs[(wrow + grp + 8) * 132 + k0 + thr + 4]);
#pragma unroll
        for (int nt = 0; nt < 16; nt++) {
            int n = nt * 8 + grp;
            uint32_t b0 = __float_as_uint(ws[(k0 + thr)     * 132 + n]);
            uint32_t b1 = __float_as_uint(ws[(k0 + thr + 4) * 132 + n]);
            asm volatile(
                "mma.sync.aligned.m16n8k8.row.col.f32.tf32.tf32.f32 "
                "{%0,%1,%2,%3}, {%4,%5,%6,%7}, {%8,%9}, {%0,%1,%2,%3};"
                : "+f"(c[nt][0]), "+f"(c[nt][1]), "+f"(c[nt][2]), "+f"(c[nt][3])
                : "r"(a0), "r"(a1), "r"(a2), "r"(a3), "r"(b0), "r"(b1));
        }
    }

    int r0 = base + wrow + grp;
    int r1 = r0 + 8;
#pragma unroll
    for (int nt = 0; nt < 16; nt++) {
        int col = nt * 8 + 2 * thr;
        if (r0 < NN)
            *(__half2*)&g_xwh[(size_t)r0 * 128 + col] =
                __floats2half2_rn(c[nt][0], c[nt][1]);
        if (r1 < NN)
            *(__half2*)&g_xwh[(size_t)r1 * 128 + col] =
                __floats2half2_rn(c[nt][2], c[nt][3]);
    }
}

// ---------------------------------------------------------------------------
// gather: warp per node, all message+self reads from fp16 (L2-resident),
// 8 edges in flight across 4 accumulators.
__device__ __forceinline__ float4 load_h4(int src, int lane) {
    uint2 raw = *(const uint2*)(g_xwh + (size_t)src * 128 + lane * 4);
    __half2 h0 = *reinterpret_cast<const __half2*>(&raw.x);
    __half2 h1 = *reinterpret_cast<const __half2*>(&raw.y);
    float2 f0 = __half22float2(h0);
    float2 f1 = __half22float2(h1);
    return make_float4(f0.x, f0.y, f1.x, f1.y);
}

__device__ __forceinline__ void fma4(float4& a, float c, const float4& v) {
    a.x += c * v.x; a.y += c * v.y; a.z += c * v.z; a.w += c * v.w;
}

__global__ void __launch_bounds__(256) gather_kernel(const float* __restrict__ bias,
                                                     const float* __restrict__ prelu_a,
                                                     float* __restrict__ out) {
    int node = (blockIdx.x * blockDim.x + threadIdx.x) >> 5;
    int lane = threadIdx.x & 31;
    if (node >= NN) return;

    int end   = g_incl[node];
    int start = end - g_cnt[node];

    float di = g_dinv[node];
    float s  = di * di;
    float4 acc0 = load_h4(node, lane);
    acc0.x *= s; acc0.y *= s; acc0.z *= s; acc0.w *= s;
    float4 acc1 = make_float4(0.f, 0.f, 0.f, 0.f);
    float4 acc2 = make_float4(0.f, 0.f, 0.f, 0.f);
    float4 acc3 = make_float4(0.f, 0.f, 0.f, 0.f);

    int e = start;
    for (; e + 8 <= end; e += 8) {
        int2 p0 = __ldg(&g_epack[e]);
        int2 p1 = __ldg(&g_epack[e + 1]);
        int2 p2 = __ldg(&g_epack[e + 2]);
        int2 p3 = __ldg(&g_epack[e + 3]);
        int2 p4 = __ldg(&g_epack[e + 4]);
        int2 p5 = __ldg(&g_epack[e + 5]);
        int2 p6 = __ldg(&g_epack[e + 6]);
        int2 p7 = __ldg(&g_epack[e + 7]);
        float4 v0 = load_h4(p0.x, lane);
        float4 v1 = load_h4(p1.x, lane);
        float4 v2 = load_h4(p2.x, lane);
        float4 v3 = load_h4(p3.x, lane);
        float4 v4 = load_h4(p4.x, lane);
        float4 v5 = load_h4(p5.x, lane);
        float4 v6 = load_h4(p6.x, lane);
        float4 v7 = load_h4(p7.x, lane);
        fma4(acc0, __int_as_float(p0.y), v0);
        fma4(acc1, __int_as_float(p1.y), v1);
        fma4(acc2, __int_as_float(p2.y), v2);
        fma4(acc3, __int_as_float(p3.y), v3);
        fma4(acc0, __int_as_float(p4.y), v4);
        fma4(acc1, __int_as_float(p5.y), v5);
        fma4(acc2, __int_as_float(p6.y), v6);
        fma4(acc3, __int_as_float(p7.y), v7);
    }
    for (; e < end; e++) {
        int2 p0 = __ldg(&g_epack[e]);
        float4 v0 = load_h4(p0.x, lane);
        fma4(acc0, __int_as_float(p0.y), v0);
    }

    float a  = __ldg(prelu_a);
    float4 b = ((const float4*)bias)[lane];
    acc0.x += acc1.x + acc2.x + acc3.x + b.x;
    acc0.y += acc1.y + acc2.y + acc3.y + b.y;
    acc0.z += acc1.z + acc2.z + acc3.z + b.z;
    acc0.w += acc1.w + acc2.w + acc3.w + b.w;
    acc0.x = (acc0.x >= 0.f) ? acc0.x : a * acc0.x;
    acc0.y = (acc0.y >= 0.f) ? acc0.y : a * acc0.y;
    acc0.z = (acc0.z >= 0.f) ? acc0.z : a * acc0.z;
    acc0.w = (acc0.w >= 0.f) ? acc0.w : a * acc0.w;

    ((float4*)out)[(size_t)node * 32 + lane] = acc0;
}

// ---------------------------------------------------------------------------
// Stream/event resources: created lazily on the FIRST kernel_launch call
// (the harness's uncaptured correctness run), never inside graph capture.
static cudaStream_t g_sB = nullptr;
static cudaEvent_t  g_evFork = nullptr, g_evJoin = nullptr;

extern "C" void kernel_launch(void* const* d_in, const int* in_sizes, int n_in,
                              void* d_out, int out_size) {
    const float* x    = (const float*)d_in[0];
    const int*   ei   = (const int*)d_in[1];     // int32 (JAX x64 disabled)
    const float* ew   = (const float*)d_in[2];
    const float* w    = (const float*)d_in[3];
    const float* bias = (const float*)d_in[4];
    const float* pa   = (const float*)d_in[5];
    float*       out  = (float*)d_out;

    (void)in_sizes; (void)n_in; (void)out_size;

    if (g_sB == nullptr) {
        cudaStreamCreateWithFlags(&g_sB, cudaStreamNonBlocking);
        cudaEventCreateWithFlags(&g_evFork, cudaEventDisableTiming);
        cudaEventCreateWithFlags(&g_evJoin, cudaEventDisableTiming);
        cudaFuncSetAttribute(gemm_kernel,
                             cudaFuncAttributeMaxDynamicSharedMemorySize,
                             GEMM_SMEM_BYTES);
    }

    // Fork: GEMM on side stream, overlapped with CSR build on main stream.
    cudaEventRecord(g_evFork, 0);
    cudaStreamWaitEvent(g_sB, g_evFork, 0);
    gemm_kernel<<<(NN + 127) / 128, 256, GEMM_SMEM_BYTES, g_sB>>>(x, w);
    cudaEventRecord(g_evJoin, g_sB);

    // Fused CSR build (init+accum+scan+fill) on main stream.
    mega_csr_kernel<<<MEGA_BLOCKS, MEGA_THREADS>>>(ei, ew);

    // Join: gather needs both branches.
    cudaStreamWaitEvent(0, g_evJoin, 0);
    gather_kernel<<<(NN * 32 + 255) / 256, 256>>>(bias, pa, out);
}

// round 15
// speedup vs baseline: 2.1436x; 2.1436x over previous
#include <cuda_runtime.h>
#include <cuda_fp16.h>
#include <cstdint>

#define NN 100000
#define EE 1600000
#define DD 128

#define SCAN_THREADS 256
#define SCAN_PER_THREAD 8
#define SCAN_CHUNK (SCAN_THREADS * SCAN_PER_THREAD)   // 2048
#define SCAN_NB ((NN + SCAN_CHUNK - 1) / SCAN_CHUNK)  // 49

// paired-float2 tf32 layout: 128 rows x 68 float2 (pad), two operands
#define GEMM_SMEM_BYTES (2 * 128 * 68 * 8)            // 139264

// Scratch (no device allocation allowed -> __device__ globals)
__device__ __half g_xwh[(size_t)NN * DD];   // x @ W fp16 (25.6 MB, L2-resident)
__device__ float  g_deg[NN];
__device__ float  g_dinv[NN];
__device__ int    g_cnt[NN];
__device__ int    g_incl[NN];
__device__ int    g_cursor[NN];
__device__ int    g_bsum[SCAN_NB];
__device__ int2   g_epack[EE];              // CSR-by-target: (src, coef bits)

// ---------------------------------------------------------------------------
// side-stream: init (deg=1 self-loop, cnt=0)
__global__ void init_kernel() {
    int i = blockIdx.x * blockDim.x + threadIdx.x;
    if (i < NN) { g_deg[i] = 1.0f; g_cnt[i] = 0; }
}

// main: degree + histogram at targets
__global__ void accum_kernel(const int* __restrict__ ei,
                             const float* __restrict__ ew) {
    int e = blockIdx.x * blockDim.x + threadIdx.x;
    if (e < EE) {
        int c = ei[EE + e];
        atomicAdd(&g_deg[c], ew[e]);
        atomicAdd(&g_cnt[c], 1);
    }
}

// ---------------------------------------------------------------------------
// scanA: per-chunk totals only
__global__ void __launch_bounds__(SCAN_THREADS) scanA_kernel() {
    __shared__ int sh[SCAN_THREADS / 32];
    int tid  = threadIdx.x;
    int base = blockIdx.x * SCAN_CHUNK + tid * SCAN_PER_THREAD;
    int sum = 0;
#pragma unroll
    for (int j = 0; j < SCAN_PER_THREAD; j++) {
        int idx = base + j;
        sum += (idx < NN) ? g_cnt[idx] : 0;
    }
#pragma unroll
    for (int off = 16; off > 0; off >>= 1)
        sum += __shfl_down_sync(0xffffffffu, sum, off);
    if ((tid & 31) == 0) sh[tid >> 5] = sum;
    __syncthreads();
    if (tid == 0) {
        int t = 0;
#pragma unroll
        for (int i = 0; i < SCAN_THREADS / 32; i++) t += sh[i];
        g_bsum[blockIdx.x] = t;
    }
}

// scanB: block b reduces g_bsum[0..b-1] (warp reduction, registers only),
// re-scans its own chunk, writes incl/cursor, computes dinv.
// No inter-block communication -> deterministic.
__global__ void __launch_bounds__(SCAN_THREADS) scanB_kernel() {
    __shared__ int sh[SCAN_THREADS];
    __shared__ int sh_prefix;
    int tid = threadIdx.x;
    int b   = blockIdx.x;

    if (tid < 32) {
        int v0 = (tid < b) ? g_bsum[tid] : 0;
        int v1 = (tid + 32 < b) ? g_bsum[tid + 32] : 0;
        int s = v0 + v1;
#pragma unroll
        for (int off = 16; off > 0; off >>= 1)
            s += __shfl_down_sync(0xffffffffu, s, off);
        if (tid == 0) sh_prefix = s;
    }

    int base = b * SCAN_CHUNK + tid * SCAN_PER_THREAD;
    int c[SCAN_PER_THREAD];
    int v[SCAN_PER_THREAD];
    int sum = 0;
#pragma unroll
    for (int j = 0; j < SCAN_PER_THREAD; j++) {
        int idx = base + j;
        c[j] = (idx < NN) ? g_cnt[idx] : 0;
        sum += c[j];
        v[j] = sum;                      // inclusive within thread
    }
    sh[tid] = sum;
    __syncthreads();                     // also orders sh_prefix for all threads
    for (int off = 1; off < SCAN_THREADS; off <<= 1) {
        int t = (tid >= off) ? sh[tid - off] : 0;
        __syncthreads();
        sh[tid] += t;
        __syncthreads();
    }
    int tprefix = ((tid > 0) ? sh[tid - 1] : 0) + sh_prefix;
#pragma unroll
    for (int j = 0; j < SCAN_PER_THREAD; j++) {
        int idx = base + j;
        if (idx < NN) {
            int incl = v[j] + tprefix;
            g_incl[idx]   = incl;
            g_cursor[idx] = incl - c[j];
            float d = g_deg[idx];
            g_dinv[idx] = (d > 0.0f) ? rsqrtf(d) : 0.0f;
        }
    }
}

// fill CSR: (src, coef) per edge, bucketed by target
__global__ void fill_kernel(const int* __restrict__ ei,
                            const float* __restrict__ ew) {
    int e = blockIdx.x * blockDim.x + threadIdx.x;
    if (e < EE) {
        int row = ei[e];
        int col = ei[EE + e];
        float coef = g_dinv[row] * ew[e] * g_dinv[col];
        int pos = atomicAdd(&g_cursor[col], 1);
        g_epack[pos] = make_int2(row, __float_as_int(coef));
    }
}

// ---------------------------------------------------------------------------
// tf32 tensor-core GEMM: g_xwh (fp16) = x @ W.
// 128x128 CTA tile; 8 warps in 2(M)x4(N): 64x32 per warp.
// Paired-float2 smem layout: fragment elements (k, k+4) adjacent -> each
// m16n8k8 fragment load is one LDS.64. 12 LDS.64 + 16 MMA per warp per k-step.
__device__ __forceinline__ float tf32r(float v) {
    uint32_t r;
    asm("cvt.rna.tf32.f32 %0, %1;" : "=r"(r) : "f"(v));
    return __uint_as_float(r);
}

__global__ void __launch_bounds__(256) gemm_kernel(const float* __restrict__ x,
                                                   const float* __restrict__ w) {
    extern __shared__ float2 smem2[];
    float2* xs2 = smem2;              // [128 r][68 pairs]
    float2* ws2 = smem2 + 128 * 68;   // [128 n][68 pairs]

    const int tid  = threadIdx.x;
    const int base = blockIdx.x * 128;

    const float4* xg = (const float4*)x;
    const float4* wg = (const float4*)w;

    // stage A: pairs (k, k+4) within each 8-k block
#pragma unroll
    for (int i = 0; i < 8; i++) {
        int idx = tid + i * 256;
        int r   = idx >> 4;          // 0..127
        int kb  = idx & 15;          // 8-k block
        float4 f0 = make_float4(0.f, 0.f, 0.f, 0.f), f1 = f0;
        if (base + r < NN) {
            f0 = xg[(size_t)(base + r) * 32 + kb * 2];
            f1 = xg[(size_t)(base + r) * 32 + kb * 2 + 1];
        }
        f0.x = tf32r(f0.x); f0.y = tf32r(f0.y); f0.z = tf32r(f0.z); f0.w = tf32r(f0.w);
        f1.x = tf32r(f1.x); f1.y = tf32r(f1.y); f1.z = tf32r(f1.z); f1.w = tf32r(f1.w);
        float4* dst = (float4*)&xs2[r * 68 + kb * 4];
        dst[0] = make_float4(f0.x, f1.x, f0.y, f1.y);
        dst[1] = make_float4(f0.z, f1.z, f0.w, f1.w);
    }
    // stage B: ws2[n][kt*4+thr] = (w[8kt+thr][n], w[8kt+thr+4][n])
#pragma unroll
    for (int i = 0; i < 8; i++) {
        int idx  = tid + i * 256;
        int n4   = idx & 31;
        int kthr = idx >> 5;         // 0..63
        int kt   = kthr >> 2;
        int thr  = kthr & 3;
        int k    = 8 * kt + thr;
        float4 u0 = wg[k * 32 + n4];
        float4 u1 = wg[(k + 4) * 32 + n4];
        u0.x = tf32r(u0.x); u0.y = tf32r(u0.y); u0.z = tf32r(u0.z); u0.w = tf32r(u0.w);
        u1.x = tf32r(u1.x); u1.y = tf32r(u1.y); u1.z = tf32r(u1.z); u1.w = tf32r(u1.w);
        int kk = kt * 4 + thr;
        ws2[(4 * n4 + 0) * 68 + kk] = make_float2(u0.x, u1.x);
        ws2[(4 * n4 + 1) * 68 + kk] = make_float2(u0.y, u1.y);
        ws2[(4 * n4 + 2) * 68 + kk] = make_float2(u0.z, u1.z);
        ws2[(4 * n4 + 3) * 68 + kk] = make_float2(u0.w, u1.w);
    }
    __syncthreads();

    const int warp = tid >> 5;
    const int lane = tid & 31;
    const int grp  = lane >> 2;     // 0..7
    const int thr  = lane & 3;      // 0..3
    const int wm   = (warp >> 2) * 64;   // warp M base (0 or 64)
    const int wn   = (warp & 3) * 32;    // warp N base (0,32,64,96)

    float acc[4][4][4];
#pragma unroll
    for (int mt = 0; mt < 4; mt++)
#pragma unroll
        for (int nt = 0; nt < 4; nt++)
#pragma unroll
            for (int j = 0; j < 4; j++) acc[mt][nt][j] = 0.0f;

#pragma unroll
    for (int kt = 0; kt < 16; kt++) {
        int kk = kt * 4 + thr;
        float2 Af[4][2];
        float2 Bf[4];
#pragma unroll
        for (int mt = 0; mt < 4; mt++) {
            Af[mt][0] = xs2[(wm + mt * 16 + grp) * 68 + kk];
            Af[mt][1] = xs2[(wm + mt * 16 + grp + 8) * 68 + kk];
        }
#pragma unroll
        for (int nt = 0; nt < 4; nt++)
            Bf[nt] = ws2[(wn + nt * 8 + grp) * 68 + kk];
#pragma unroll
        for (int mt = 0; mt < 4; mt++) {
            uint32_t a0 = __float_as_uint(Af[mt][0].x);
            uint32_t a1 = __float_as_uint(Af[mt][1].x);
            uint32_t a2 = __float_as_uint(Af[mt][0].y);
            uint32_t a3 = __float_as_uint(Af[mt][1].y);
#pragma unroll
            for (int nt = 0; nt < 4; nt++) {
                uint32_t b0 = __float_as_uint(Bf[nt].x);
                uint32_t b1 = __float_as_uint(Bf[nt].y);
                asm volatile(
                    "mma.sync.aligned.m16n8k8.row.col.f32.tf32.tf32.f32 "
                    "{%0,%1,%2,%3}, {%4,%5,%6,%7}, {%8,%9}, {%0,%1,%2,%3};"
                    : "+f"(acc[mt][nt][0]), "+f"(acc[mt][nt][1]),
                      "+f"(acc[mt][nt][2]), "+f"(acc[mt][nt][3])
                    : "r"(a0), "r"(a1), "r"(a2), "r"(a3), "r"(b0), "r"(b1));
            }
        }
    }

#pragma unroll
    for (int mt = 0; mt < 4; mt++) {
        int r0 = base + wm + mt * 16 + grp;
        int r1 = r0 + 8;
#pragma unroll
        for (int nt = 0; nt < 4; nt++) {
            int col = wn + nt * 8 + 2 * thr;
            if (r0 < NN)
                *(__half2*)&g_xwh[(size_t)r0 * 128 + col] =
                    __floats2half2_rn(acc[mt][nt][0], acc[mt][nt][1]);
            if (r1 < NN)
                *(__half2*)&g_xwh[(size_t)r1 * 128 + col] =
                    __floats2half2_rn(acc[mt][nt][2], acc[mt][nt][3]);
        }
    }
}

// ---------------------------------------------------------------------------
// gather: warp per node, fp16 messages (L2-resident), 8 edges in flight.
__device__ __forceinline__ float4 load_h4(int src, int lane) {
    uint2 raw = *(const uint2*)(g_xwh + (size_t)src * 128 + lane * 4);
    __half2 h0 = *reinterpret_cast<const __half2*>(&raw.x);
    __half2 h1 = *reinterpret_cast<const __half2*>(&raw.y);
    float2 f0 = __half22float2(h0);
    float2 f1 = __half22float2(h1);
    return make_float4(f0.x, f0.y, f1.x, f1.y);
}

__device__ __forceinline__ void fma4(float4& a, float c, const float4& v) {
    a.x += c * v.x; a.y += c * v.y; a.z += c * v.z; a.w += c * v.w;
}

__global__ void __launch_bounds__(256) gather_kernel(const float* __restrict__ bias,
                                                     const float* __restrict__ prelu_a,
                                                     float* __restrict__ out) {
    int node = (blockIdx.x * blockDim.x + threadIdx.x) >> 5;
    int lane = threadIdx.x & 31;
    if (node >= NN) return;

    int end   = g_incl[node];
    int start = end - g_cnt[node];

    float di = g_dinv[node];
    float s  = di * di;
    float4 acc0 = load_h4(node, lane);
    acc0.x *= s; acc0.y *= s; acc0.z *= s; acc0.w *= s;
    float4 acc1 = make_float4(0.f, 0.f, 0.f, 0.f);
    float4 acc2 = make_float4(0.f, 0.f, 0.f, 0.f);
    float4 acc3 = make_float4(0.f, 0.f, 0.f, 0.f);

    int e = start;
    for (; e + 8 <= end; e += 8) {
        int2 p0 = __ldg(&g_epack[e]);
        int2 p1 = __ldg(&g_epack[e + 1]);
        int2 p2 = __ldg(&g_epack[e + 2]);
        int2 p3 = __ldg(&g_epack[e + 3]);
        int2 p4 = __ldg(&g_epack[e + 4]);
        int2 p5 = __ldg(&g_epack[e + 5]);
        int2 p6 = __ldg(&g_epack[e + 6]);
        int2 p7 = __ldg(&g_epack[e + 7]);
        float4 v0 = load_h4(p0.x, lane);
        float4 v1 = load_h4(p1.x, lane);
        float4 v2 = load_h4(p2.x, lane);
        float4 v3 = load_h4(p3.x, lane);
        float4 v4 = load_h4(p4.x, lane);
        float4 v5 = load_h4(p5.x, lane);
        float4 v6 = load_h4(p6.x, lane);
        float4 v7 = load_h4(p7.x, lane);
        fma4(acc0, __int_as_float(p0.y), v0);
        fma4(acc1, __int_as_float(p1.y), v1);
        fma4(acc2, __int_as_float(p2.y), v2);
        fma4(acc3, __int_as_float(p3.y), v3);
        fma4(acc0, __int_as_float(p4.y), v4);
        fma4(acc1, __int_as_float(p5.y), v5);
        fma4(acc2, __int_as_float(p6.y), v6);
        fma4(acc3, __int_as_float(p7.y), v7);
    }
    for (; e < end; e++) {
        int2 p0 = __ldg(&g_epack[e]);
        float4 v0 = load_h4(p0.x, lane);
        fma4(acc0, __int_as_float(p0.y), v0);
    }

    float a  = __ldg(prelu_a);
    float4 b = ((const float4*)bias)[lane];
    acc0.x += acc1.x + acc2.x + acc3.x + b.x;
    acc0.y += acc1.y + acc2.y + acc3.y + b.y;
    acc0.z += acc1.z + acc2.z + acc3.z + b.z;
    acc0.w += acc1.w + acc2.w + acc3.w + b.w;
    acc0.x = (acc0.x >= 0.f) ? acc0.x : a * acc0.x;
    acc0.y = (acc0.y >= 0.f) ? acc0.y : a * acc0.y;
    acc0.z = (acc0.z >= 0.f) ? acc0.z : a * acc0.z;
    acc0.w = (acc0.w >= 0.f) ? acc0.w : a * acc0.w;

    ((float4*)out)[(size_t)node * 32 + lane] = acc0;
}

// ---------------------------------------------------------------------------
// Stream/event resources: created lazily on the FIRST kernel_launch call
// (the harness's uncaptured correctness run), never inside graph capture.
static cudaStream_t g_sB = nullptr;
static cudaEvent_t  g_evFork = nullptr, g_evInit = nullptr, g_evJoin = nullptr;

extern "C" void kernel_launch(void* const* d_in, const int* in_sizes, int n_in,
                              void* d_out, int out_size) {
    const float* x    = (const float*)d_in[0];
    const int*   ei   = (const int*)d_in[1];     // int32 (JAX x64 disabled)
    const float* ew   = (const float*)d_in[2];
    const float* w    = (const float*)d_in[3];
    const float* bias = (const float*)d_in[4];
    const float* pa   = (const float*)d_in[5];
    float*       out  = (float*)d_out;

    (void)in_sizes; (void)n_in; (void)out_size;

    if (g_sB == nullptr) {
        cudaStreamCreateWithFlags(&g_sB, cudaStreamNonBlocking);
        cudaEventCreateWithFlags(&g_evFork, cudaEventDisableTiming);
        cudaEventCreateWithFlags(&g_evInit, cudaEventDisableTiming);
        cudaEventCreateWithFlags(&g_evJoin, cudaEventDisableTiming);
        cudaFuncSetAttribute(gemm_kernel,
                             cudaFuncAttributeMaxDynamicSharedMemorySize,
                             GEMM_SMEM_BYTES);
    }

    // Fork: init + GEMM on side stream.
    cudaEventRecord(g_evFork, 0);
    cudaStreamWaitEvent(g_sB, g_evFork, 0);
    init_kernel<<<(NN + 255) / 256, 256, 0, g_sB>>>();
    cudaEventRecord(g_evInit, g_sB);
    gemm_kernel<<<(NN + 127) / 128, 256, GEMM_SMEM_BYTES, g_sB>>>(x, w);
    cudaEventRecord(g_evJoin, g_sB);

    // Main stream: CSR build (needs init done).
    cudaStreamWaitEvent(0, g_evInit, 0);
    accum_kernel<<<(EE + 255) / 256, 256>>>(ei, ew);
    scanA_kernel<<<SCAN_NB, SCAN_THREADS>>>();
    scanB_kernel<<<SCAN_NB, SCAN_THREADS>>>();
    fill_kernel<<<(EE + 255) / 256, 256>>>(ei, ew);

    // Join: gather needs GEMM + CSR.
    cudaStreamWaitEvent(0, g_evJoin, 0);
    gather_kernel<<<(NN * 32 + 255) / 256, 256>>>(bias, pa, out);
}